// round 3
// baseline (speedup 1.0000x reference)
#include <cuda_runtime.h>
#include <math.h>
#include <stdint.h>

#define SEQ   512
#define BATCH 64
#define NIN   1024
#define NHID  1024
#define G4    4096   // 4*NHID

// ---------------------------------------------------------------------------
// Scratch (device globals; no allocation allowed in kernel_launch)
// ---------------------------------------------------------------------------
__device__ float g_xw[(size_t)SEQ * BATCH * G4];     // 512 MB : x@w_x^T + bias
__device__ float g_hs[(size_t)SEQ * BATCH * NHID];   // 128 MB : h_1..h_512
__device__ float g_c [(size_t)BATCH * NHID];         // carried cell state

// ---------------------------------------------------------------------------
// f32x2 packed helpers (Blackwell sm_100a)
// ---------------------------------------------------------------------------
__device__ __forceinline__ unsigned long long pk2(float x) {
    unsigned long long r;
    asm("mov.b64 %0, {%1, %1};" : "=l"(r) : "f"(x));
    return r;
}
__device__ __forceinline__ unsigned long long pk2b(float lo, float hi) {
    unsigned long long r;
    asm("mov.b64 %0, {%1, %2};" : "=l"(r) : "f"(lo), "f"(hi));
    return r;
}
__device__ __forceinline__ void upk2(unsigned long long v, float& lo, float& hi) {
    asm("mov.b64 {%0, %1}, %2;" : "=f"(lo), "=f"(hi) : "l"(v));
}
__device__ __forceinline__ void ffma2(unsigned long long& d,
                                      unsigned long long a,
                                      unsigned long long b) {
    asm("fma.rn.f32x2 %0, %1, %2, %0;" : "+l"(d) : "l"(a), "l"(b));
}

// ---------------------------------------------------------------------------
// GEMM: C[M,N] = A[M,K] @ B[N,K]^T (+ bias[N] if bias != nullptr)
// 128x128 tile, BK=8, 256 threads, 8x8 per thread, double-buffered smem,
// f32x2 packed FMA.
// ---------------------------------------------------------------------------
__global__ void __launch_bounds__(256) gemm_nt_bias(
    const float* __restrict__ A,
    const float* __restrict__ B,
    const float* __restrict__ bias,
    float* __restrict__ C,
    int M, int N, int K)
{
    __shared__ float As[2][8][128];
    __shared__ float Bs[2][8][128];

    const int tid  = threadIdx.x;
    const int row0 = blockIdx.y * 128;
    const int col0 = blockIdx.x * 128;

    const int lr = tid >> 1;          // 0..127 (row within tile to load)
    const int lc = (tid & 1) << 2;    // 0 or 4 (k offset, float4)

    const int tx = tid & 15;          // output col group
    const int ty = tid >> 4;          // output row group

    unsigned long long acc2[8][4];
#pragma unroll
    for (int i = 0; i < 8; i++)
#pragma unroll
        for (int j = 0; j < 4; j++) acc2[i][j] = 0ull;

    const float* Ab = A + (size_t)row0 * K;
    const float* Bb = B + (size_t)col0 * K;

    const int nT = K / 8;

    // prologue: load tile 0, store buf 0
    float4 a4 = *(const float4*)(Ab + (size_t)lr * K + lc);
    float4 b4 = *(const float4*)(Bb + (size_t)lr * K + lc);
    As[0][lc + 0][lr] = a4.x; As[0][lc + 1][lr] = a4.y;
    As[0][lc + 2][lr] = a4.z; As[0][lc + 3][lr] = a4.w;
    Bs[0][lc + 0][lr] = b4.x; Bs[0][lc + 1][lr] = b4.y;
    Bs[0][lc + 2][lr] = b4.z; Bs[0][lc + 3][lr] = b4.w;
    __syncthreads();

    for (int kt = 0; kt < nT; kt++) {
        const int cur = kt & 1;
        if (kt + 1 < nT) {
            const int k0 = (kt + 1) * 8;
            a4 = *(const float4*)(Ab + (size_t)lr * K + k0 + lc);
            b4 = *(const float4*)(Bb + (size_t)lr * K + k0 + lc);
        }
#pragma unroll
        for (int k = 0; k < 8; k++) {
            float ra[8];
            *(float4*)&ra[0] = *(const float4*)&As[cur][k][ty * 8];
            *(float4*)&ra[4] = *(const float4*)&As[cur][k][ty * 8 + 4];
            ulonglong2 rb0 = *(const ulonglong2*)&Bs[cur][k][tx * 8];
            ulonglong2 rb1 = *(const ulonglong2*)&Bs[cur][k][tx * 8 + 4];
#pragma unroll
            for (int i = 0; i < 8; i++) {
                const unsigned long long pa = pk2(ra[i]);
                ffma2(acc2[i][0], pa, rb0.x);
                ffma2(acc2[i][1], pa, rb0.y);
                ffma2(acc2[i][2], pa, rb1.x);
                ffma2(acc2[i][3], pa, rb1.y);
            }
        }
        if (kt + 1 < nT) {
            const int nxt = cur ^ 1;
            As[nxt][lc + 0][lr] = a4.x; As[nxt][lc + 1][lr] = a4.y;
            As[nxt][lc + 2][lr] = a4.z; As[nxt][lc + 3][lr] = a4.w;
            Bs[nxt][lc + 0][lr] = b4.x; Bs[nxt][lc + 1][lr] = b4.y;
            Bs[nxt][lc + 2][lr] = b4.z; Bs[nxt][lc + 3][lr] = b4.w;
            __syncthreads();
        }
    }

#pragma unroll
    for (int i = 0; i < 8; i++) {
        const int r = row0 + ty * 8 + i;
        float av[8];
#pragma unroll
        for (int j = 0; j < 4; j++) upk2(acc2[i][j], av[2 * j], av[2 * j + 1]);
#pragma unroll
        for (int j = 0; j < 8; j += 4) {
            const int c = col0 + tx * 8 + j;
            float4 v;
            v.x = av[j + 0]; v.y = av[j + 1];
            v.z = av[j + 2]; v.w = av[j + 3];
            if (bias) {
                v.x += bias[c + 0]; v.y += bias[c + 1];
                v.z += bias[c + 2]; v.w += bias[c + 3];
            }
            *(float4*)(C + (size_t)r * N + c) = v;
        }
    }
}

// ---------------------------------------------------------------------------
// One LSTM timestep (fused: a = xw_t + h@w_h^T, gates, c/h update).
// Grid: 128 blocks (8 hidden units each), 256 threads.
// Thread (bg, jl): batches {2*bg, 2*bg+1}, unit j0+jl, all 4 gates.
// Accumulators packed over gate pairs (f32x2). Double-buffered smem.
// Inner loop per k: LDS.64 (h pair) + LDS.128 (w quad) + 2 pack + 4 FFMA2.
// ---------------------------------------------------------------------------
__global__ void __launch_bounds__(256) lstm_step(
    const float* __restrict__ xw_t,   // [BATCH][G4]
    const float* __restrict__ h_in,   // [BATCH][NHID]
    const float* __restrict__ c_in,   // [BATCH][NHID]
    const float* __restrict__ w_h,    // [G4][NHID]
    float* __restrict__ h_out,        // [BATCH][NHID]
    float* __restrict__ c_out)        // [BATCH][NHID]
{
    const int KT = 64;
    __shared__ float hs[2][KT][BATCH];   // [buf][k][b]       32 KB
    __shared__ float ws[2][KT][32];      // [buf][k][jl*4+g]  16 KB

    const int tid = threadIdx.x;
    const int j0  = blockIdx.x * 8;
    const int bg  = tid >> 3;         // 0..31
    const int jl  = tid & 7;          // 0..7
    const int b0  = bg * 2;
    const int j   = j0 + jl;

    // prefetch cell state early
    const float cp0 = c_in[(size_t)(b0    ) * NHID + j];
    const float cp1 = c_in[(size_t)(b0 + 1) * NHID + j];

    // acc2[b][p]: lanes = gates (2p, 2p+1) for batch b0+b
    unsigned long long acc2[2][2];
#pragma unroll
    for (int bb = 0; bb < 2; bb++) {
        const size_t base = (size_t)(b0 + bb) * G4 + j;
        acc2[bb][0] = pk2b(xw_t[base + 0 * NHID], xw_t[base + 1 * NHID]);
        acc2[bb][1] = pk2b(xw_t[base + 2 * NHID], xw_t[base + 3 * NHID]);
    }

    // staging register loads for a K-tile
    float4 hstage[4], wstage[2];
    int hb[4], hk[4], wr[2], wk[2];
#pragma unroll
    for (int q = 0; q < 4; q++) {
        const int s = tid + 256 * q;
        hb[q] = s & 63;
        hk[q] = s >> 6;               // 0..15 (float4 index along k)
    }
#pragma unroll
    for (int q = 0; q < 2; q++) {
        const int s = tid + 256 * q;
        wr[q] = s & 31;               // jj*4+g
        wk[q] = s >> 5;               // 0..15
    }

    // prologue: load tile 0, store buf 0
#pragma unroll
    for (int q = 0; q < 4; q++)
        hstage[q] = *(const float4*)(h_in + (size_t)hb[q] * NHID + hk[q] * 4);
#pragma unroll
    for (int q = 0; q < 2; q++) {
        const int jj = wr[q] >> 2, g = wr[q] & 3;
        wstage[q] = *(const float4*)(w_h + (size_t)(g * NHID + j0 + jj) * NHID
                                          + wk[q] * 4);
    }
#pragma unroll
    for (int q = 0; q < 4; q++) {
        hs[0][hk[q] * 4 + 0][hb[q]] = hstage[q].x;
        hs[0][hk[q] * 4 + 1][hb[q]] = hstage[q].y;
        hs[0][hk[q] * 4 + 2][hb[q]] = hstage[q].z;
        hs[0][hk[q] * 4 + 3][hb[q]] = hstage[q].w;
    }
#pragma unroll
    for (int q = 0; q < 2; q++) {
        ws[0][wk[q] * 4 + 0][wr[q]] = wstage[q].x;
        ws[0][wk[q] * 4 + 1][wr[q]] = wstage[q].y;
        ws[0][wk[q] * 4 + 2][wr[q]] = wstage[q].z;
        ws[0][wk[q] * 4 + 3][wr[q]] = wstage[q].w;
    }
    __syncthreads();

    const int nT = NHID / KT;   // 16
    for (int kt = 0; kt < nT; kt++) {
        const int cur = kt & 1;
        if (kt + 1 < nT) {
            const int k0 = (kt + 1) * KT;
#pragma unroll
            for (int q = 0; q < 4; q++)
                hstage[q] = *(const float4*)(h_in + (size_t)hb[q] * NHID
                                                  + k0 + hk[q] * 4);
#pragma unroll
            for (int q = 0; q < 2; q++) {
                const int jj = wr[q] >> 2, g = wr[q] & 3;
                wstage[q] = *(const float4*)(w_h
                              + (size_t)(g * NHID + j0 + jj) * NHID
                              + k0 + wk[q] * 4);
            }
        }
#pragma unroll
        for (int k = 0; k < KT; k++) {
            const float2 hv = *(const float2*)&hs[cur][k][b0];
            const ulonglong2 wv = *(const ulonglong2*)&ws[cur][k][jl * 4];
            const unsigned long long hx = pk2(hv.x);
            const unsigned long long hy = pk2(hv.y);
            ffma2(acc2[0][0], hx, wv.x);
            ffma2(acc2[0][1], hx, wv.y);
            ffma2(acc2[1][0], hy, wv.x);
            ffma2(acc2[1][1], hy, wv.y);
        }
        if (kt + 1 < nT) {
            const int nxt = cur ^ 1;
#pragma unroll
            for (int q = 0; q < 4; q++) {
                hs[nxt][hk[q] * 4 + 0][hb[q]] = hstage[q].x;
                hs[nxt][hk[q] * 4 + 1][hb[q]] = hstage[q].y;
                hs[nxt][hk[q] * 4 + 2][hb[q]] = hstage[q].z;
                hs[nxt][hk[q] * 4 + 3][hb[q]] = hstage[q].w;
            }
#pragma unroll
            for (int q = 0; q < 2; q++) {
                ws[nxt][wk[q] * 4 + 0][wr[q]] = wstage[q].x;
                ws[nxt][wk[q] * 4 + 1][wr[q]] = wstage[q].y;
                ws[nxt][wk[q] * 4 + 2][wr[q]] = wstage[q].z;
                ws[nxt][wk[q] * 4 + 3][wr[q]] = wstage[q].w;
            }
            __syncthreads();
        }
    }

    // epilogue: gates + state update
    const float cps[2] = {cp0, cp1};
#pragma unroll
    for (int bb = 0; bb < 2; bb++) {
        float a_i, a_f, a_o, a_g;
        upk2(acc2[bb][0], a_i, a_f);
        upk2(acc2[bb][1], a_o, a_g);
        const float i_ = 1.f / (1.f + expf(-a_i));
        const float f_ = 1.f / (1.f + expf(-a_f));
        const float o_ = 1.f / (1.f + expf(-a_o));
        const float gg = tanhf(a_g);
        const float cn = f_ * cps[bb] + i_ * gg;
        const int b = b0 + bb;
        c_out[(size_t)b * NHID + j] = cn;
        h_out[(size_t)b * NHID + j] = o_ * tanhf(cn);
    }
}

// ---------------------------------------------------------------------------
// Write final h and c into the output tail.
// ---------------------------------------------------------------------------
__global__ void copy_tail(float* __restrict__ out_h, float* __restrict__ out_c)
{
    const int i = blockIdx.x * blockDim.x + threadIdx.x;
    if (i < BATCH * NHID) {
        out_h[i] = g_hs[(size_t)(SEQ - 1) * BATCH * NHID + i];
        out_c[i] = g_c[i];
    }
}

// ---------------------------------------------------------------------------
// kernel_launch: graph-capturable, allocation-free.
// Inputs: x, h, c, w_x, w_h, bias, w_o. Output: [pred(512*64*1024) | h | c].
// ---------------------------------------------------------------------------
extern "C" void kernel_launch(void* const* d_in, const int* in_sizes, int n_in,
                              void* d_out, int out_size)
{
    const float* x    = (const float*)d_in[0];
    const float* h0   = (const float*)d_in[1];
    const float* c0   = (const float*)d_in[2];
    const float* w_x  = (const float*)d_in[3];
    const float* w_h  = (const float*)d_in[4];
    const float* bias = (const float*)d_in[5];
    const float* w_o  = (const float*)d_in[6];
    float* out = (float*)d_out;

    float *xw, *hs, *cbuf;
    cudaGetSymbolAddress((void**)&xw,   g_xw);
    cudaGetSymbolAddress((void**)&hs,   g_hs);
    cudaGetSymbolAddress((void**)&cbuf, g_c);

    // Phase 1: xw = x @ w_x^T + bias   [32768 x 4096]
    {
        dim3 grid(G4 / 128, (SEQ * BATCH) / 128);
        gemm_nt_bias<<<grid, 256>>>(x, w_x, bias, xw, SEQ * BATCH, G4, NIN);
    }

    // Phase 2: sequential recurrence (512 graph nodes)
    for (int t = 0; t < SEQ; t++) {
        const float* h_in = (t == 0) ? h0 : hs + (size_t)(t - 1) * BATCH * NHID;
        const float* c_in = (t == 0) ? c0 : cbuf;
        lstm_step<<<NHID / 8, 256>>>(xw + (size_t)t * BATCH * G4,
                                     h_in, c_in, w_h,
                                     hs + (size_t)t * BATCH * NHID, cbuf);
    }

    // Phase 3: pred = H @ w_o^T   [32768 x 1024]
    {
        dim3 grid(NHID / 128, (SEQ * BATCH) / 128);
        gemm_nt_bias<<<grid, 256>>>(hs, w_o, nullptr, out, SEQ * BATCH, NHID, NHID);
    }

    // Tail: final h, c
    copy_tail<<<(BATCH * NHID + 255) / 256, 256>>>(
        out + (size_t)SEQ * BATCH * NHID,
        out + (size_t)SEQ * BATCH * NHID + BATCH * NHID);
}

// round 4
// speedup vs baseline: 1.5241x; 1.5241x over previous
#include <cuda_runtime.h>
#include <math.h>
#include <stdint.h>

#define SEQ   512
#define BATCH 64
#define NIN   1024
#define NHID  1024
#define G4    4096
#define NBLK  128
#define NTHR  512

__device__ float g_xw[(size_t)SEQ * BATCH * G4];
__device__ float g_hs[(size_t)SEQ * BATCH * NHID];
__device__ float g_c [(size_t)BATCH * NHID];
__device__ unsigned g_arr;
__device__ unsigned g_gen;

__device__ __forceinline__ unsigned long long pk2(float x) {
    unsigned long long r;
    asm("mov.b64 %0, {%1, %1};" : "=l"(r) : "f"(x));
    return r;
}
__device__ __forceinline__ void upk2(unsigned long long v, float& lo, float& hi) {
    asm("mov.b64 {%0, %1}, %2;" : "=f"(lo), "=f"(hi) : "l"(v));
}
__device__ __forceinline__ void ffma2(unsigned long long& d,
                                      unsigned long long a,
                                      unsigned long long b) {
    asm("fma.rn.f32x2 %0, %1, %2, %0;" : "+l"(d) : "l"(a), "l"(b));
}
__device__ __forceinline__ void cp16(void* dst, const void* src) {
    unsigned d = (unsigned)__cvta_generic_to_shared(dst);
    asm volatile("cp.async.cg.shared.global [%0], [%1], 16;\n" :: "r"(d), "l"(src));
}

// ---------------------------------------------------------------------------
// Persistent LSTM recurrence. 128 blocks x 512 thr, all co-resident.
// smem: [0,131072) ws = w slice [k=1024][r=32]; [131072,+32K) hs buf0;
//       [+32K,+64K) hs buf1 ([b=64][k=128] floats, rows 512B);
//       reduction (8*512*16B = 64KB) aliases the hs buffers.
// Thread id = qk(8) x bg(8) x jl(8): k-eighth, batch-group(8), unit lane.
// ---------------------------------------------------------------------------
__global__ void __launch_bounds__(NTHR, 1) lstm_persist(
    const float* __restrict__ h0,
    const float* __restrict__ c0,
    const float* __restrict__ w_h)
{
    extern __shared__ char smem[];
    float* ws = (float*)smem;
    char* hsb[2] = { smem + 131072, smem + 131072 + 32768 };
    char* red    = smem + 131072;

    const int tid = threadIdx.x;
    const int j0  = blockIdx.x * 8;
    const int qk  = tid >> 6;
    const int bg  = (tid >> 3) & 7;
    const int jl  = tid & 7;
    const int b0  = bg * 8;
    // epilogue identity: slot2 = b*8 + jl  ->  b = tid>>3, jl = tid&7
    const int eb  = tid >> 3;
    const int ej  = j0 + (tid & 7);

    // w slice once: [g*NHID + j0+jj][k] -> ws[k*32 + jj*4+g]
#pragma unroll
    for (int q = 0; q < 16; q++) {
        const int s  = tid + NTHR * q;
        const int r  = s & 31;
        const int k4 = s >> 5;
        const int g  = r & 3, jj = r >> 2;
        const float4 v = *(const float4*)(w_h
            + (size_t)(g * NHID + j0 + jj) * NHID + k4 * 4);
        ws[(k4 * 4 + 0) * 32 + r] = v.x;
        ws[(k4 * 4 + 1) * 32 + r] = v.y;
        ws[(k4 * 4 + 2) * 32 + r] = v.z;
        ws[(k4 * 4 + 3) * 32 + r] = v.w;
    }

    float creg = c0[(size_t)eb * NHID + ej];
    __syncthreads();

    for (int t = 0; t < SEQ; t++) {
        const float* hp = t ? (g_hs + (size_t)(t - 1) * BATCH * NHID) : h0;

        float xwv[4];
        {
            const float* xwt = g_xw + (size_t)t * BATCH * G4
                                    + (size_t)eb * G4 + ej;
#pragma unroll
            for (int g = 0; g < 4; g++) xwv[g] = xwt[g * NHID];
        }

        unsigned long long acc[8][2];
#pragma unroll
        for (int i = 0; i < 8; i++) { acc[i][0] = 0ull; acc[i][1] = 0ull; }

        // prologue: tile 0 -> buf 0
#pragma unroll
        for (int q = 0; q < 4; q++) {
            const int s = tid + NTHR * q;
            const int b = s >> 5, cc = s & 31;
            cp16(hsb[0] + b * 512 + cc * 16, hp + (size_t)b * NHID + cc * 4);
        }
        asm volatile("cp.async.commit_group;\n" ::);

        int buf = 0;
        for (int tile = 0; tile < 8; tile++) {
            asm volatile("cp.async.wait_group 0;\n" ::);
            __syncthreads();
            if (tile < 7) {
                char* db = hsb[buf ^ 1];
                const int k0 = (tile + 1) * 128;
#pragma unroll
                for (int q = 0; q < 4; q++) {
                    const int s = tid + NTHR * q;
                    const int b = s >> 5, cc = s & 31;
                    cp16(db + b * 512 + cc * 16,
                         hp + (size_t)b * NHID + k0 + cc * 4);
                }
                asm volatile("cp.async.commit_group;\n" ::);
            }
            const char* hb = hsb[buf];
#pragma unroll
            for (int u = 0; u < 4; u++) {
                const int c16 = qk * 4 + u;
                float4 h4[8];
#pragma unroll
                for (int i = 0; i < 8; i++)
                    h4[i] = *(const float4*)(hb + (b0 + i) * 512 + c16 * 16);
#pragma unroll
                for (int kk = 0; kk < 4; kk++) {
                    const int k = tile * 128 + qk * 16 + u * 4 + kk;
                    const ulonglong2 wv = *(const ulonglong2*)(ws + k * 32 + jl * 4);
#pragma unroll
                    for (int i = 0; i < 8; i++) {
                        const unsigned long long hv = pk2((&h4[i].x)[kk]);
                        ffma2(acc[i][0], hv, wv.x);
                        ffma2(acc[i][1], hv, wv.y);
                    }
                }
            }
            buf ^= 1;
        }

        __syncthreads();   // tile reads done before red overwrites hs
#pragma unroll
        for (int i = 0; i < 8; i++) {
            const int slot2 = (b0 + i) * 8 + jl;
            ulonglong2 v; v.x = acc[i][0]; v.y = acc[i][1];
            *(ulonglong2*)(red + (((unsigned)(qk * 512 + slot2)) << 4)) = v;
        }
        __syncthreads();

        float a0 = xwv[0], a1 = xwv[1], a2 = xwv[2], a3 = xwv[3];
#pragma unroll
        for (int q2 = 0; q2 < 8; q2++) {
            const float4 v = *(const float4*)(red
                + (((unsigned)(q2 * 512 + tid)) << 4));
            a0 += v.x; a1 += v.y; a2 += v.z; a3 += v.w;
        }
        const float iS = 1.f / (1.f + expf(-a0));
        const float fS = 1.f / (1.f + expf(-a1));
        const float oS = 1.f / (1.f + expf(-a2));
        const float gT = tanhf(a3);
        creg = fS * creg + iS * gT;
        g_hs[(size_t)t * BATCH * NHID + (size_t)eb * NHID + ej]
            = oS * tanhf(creg);

        // grid barrier
        __threadfence();
        __syncthreads();
        if (tid == 0) {
            volatile unsigned* gp = &g_gen;
            const unsigned old = *gp;
            __threadfence();
            if (atomicAdd(&g_arr, 1u) == NBLK - 1) {
                atomicExch(&g_arr, 0u);
                __threadfence();
                atomicAdd(&g_gen, 1u);
            } else {
                while (*gp == old) { }
            }
            __threadfence();
        }
        __syncthreads();
    }

    g_c[(size_t)eb * NHID + ej] = creg;
}

// ---------------------------------------------------------------------------
// GEMM: C[M,N] = A[M,K] @ B[N,K]^T (+bias). 128x128, double-buffered, f32x2.
// ---------------------------------------------------------------------------
__global__ void __launch_bounds__(256) gemm_nt_bias(
    const float* __restrict__ A, const float* __restrict__ B,
    const float* __restrict__ bias, float* __restrict__ C,
    int M, int N, int K)
{
    __shared__ float As[2][8][128];
    __shared__ float Bs[2][8][128];
    const int tid  = threadIdx.x;
    const int row0 = blockIdx.y * 128;
    const int col0 = blockIdx.x * 128;
    const int lr = tid >> 1;
    const int lc = (tid & 1) << 2;
    const int tx = tid & 15;
    const int ty = tid >> 4;

    unsigned long long acc2[8][4];
#pragma unroll
    for (int i = 0; i < 8; i++)
#pragma unroll
        for (int j = 0; j < 4; j++) acc2[i][j] = 0ull;

    const float* Ab = A + (size_t)row0 * K;
    const float* Bb = B + (size_t)col0 * K;
    const int nT = K / 8;

    float4 a4 = *(const float4*)(Ab + (size_t)lr * K + lc);
    float4 b4 = *(const float4*)(Bb + (size_t)lr * K + lc);
    As[0][lc + 0][lr] = a4.x; As[0][lc + 1][lr] = a4.y;
    As[0][lc + 2][lr] = a4.z; As[0][lc + 3][lr] = a4.w;
    Bs[0][lc + 0][lr] = b4.x; Bs[0][lc + 1][lr] = b4.y;
    Bs[0][lc + 2][lr] = b4.z; Bs[0][lc + 3][lr] = b4.w;
    __syncthreads();

    for (int kt = 0; kt < nT; kt++) {
        const int cur = kt & 1;
        if (kt + 1 < nT) {
            const int k0 = (kt + 1) * 8;
            a4 = *(const float4*)(Ab + (size_t)lr * K + k0 + lc);
            b4 = *(const float4*)(Bb + (size_t)lr * K + k0 + lc);
        }
#pragma unroll
        for (int k = 0; k < 8; k++) {
            float ra[8];
            *(float4*)&ra[0] = *(const float4*)&As[cur][k][ty * 8];
            *(float4*)&ra[4] = *(const float4*)&As[cur][k][ty * 8 + 4];
            ulonglong2 rb0 = *(const ulonglong2*)&Bs[cur][k][tx * 8];
            ulonglong2 rb1 = *(const ulonglong2*)&Bs[cur][k][tx * 8 + 4];
#pragma unroll
            for (int i = 0; i < 8; i++) {
                const unsigned long long pa = pk2(ra[i]);
                ffma2(acc2[i][0], pa, rb0.x);
                ffma2(acc2[i][1], pa, rb0.y);
                ffma2(acc2[i][2], pa, rb1.x);
                ffma2(acc2[i][3], pa, rb1.y);
            }
        }
        if (kt + 1 < nT) {
            const int nxt = cur ^ 1;
            As[nxt][lc + 0][lr] = a4.x; As[nxt][lc + 1][lr] = a4.y;
            As[nxt][lc + 2][lr] = a4.z; As[nxt][lc + 3][lr] = a4.w;
            Bs[nxt][lc + 0][lr] = b4.x; Bs[nxt][lc + 1][lr] = b4.y;
            Bs[nxt][lc + 2][lr] = b4.z; Bs[nxt][lc + 3][lr] = b4.w;
            __syncthreads();
        }
    }

#pragma unroll
    for (int i = 0; i < 8; i++) {
        const int r = row0 + ty * 8 + i;
        float av[8];
#pragma unroll
        for (int j = 0; j < 4; j++) upk2(acc2[i][j], av[2 * j], av[2 * j + 1]);
#pragma unroll
        for (int j = 0; j < 8; j += 4) {
            const int c = col0 + tx * 8 + j;
            float4 v;
            v.x = av[j + 0]; v.y = av[j + 1];
            v.z = av[j + 2]; v.w = av[j + 3];
            if (bias) {
                v.x += bias[c + 0]; v.y += bias[c + 1];
                v.z += bias[c + 2]; v.w += bias[c + 3];
            }
            *(float4*)(C + (size_t)r * N + c) = v;
        }
    }
}

__global__ void copy_tail(float* __restrict__ out_h, float* __restrict__ out_c)
{
    const int i = blockIdx.x * blockDim.x + threadIdx.x;
    if (i < BATCH * NHID) {
        out_h[i] = g_hs[(size_t)(SEQ - 1) * BATCH * NHID + i];
        out_c[i] = g_c[i];
    }
}

extern "C" void kernel_launch(void* const* d_in, const int* in_sizes, int n_in,
                              void* d_out, int out_size)
{
    const float* x    = (const float*)d_in[0];
    const float* h0   = (const float*)d_in[1];
    const float* c0   = (const float*)d_in[2];
    const float* w_x  = (const float*)d_in[3];
    const float* w_h  = (const float*)d_in[4];
    const float* bias = (const float*)d_in[5];
    const float* w_o  = (const float*)d_in[6];
    float* out = (float*)d_out;

    float *xw, *hs;
    cudaGetSymbolAddress((void**)&xw, g_xw);
    cudaGetSymbolAddress((void**)&hs, g_hs);

    static int smem_set = 0;
    if (!smem_set) {
        cudaFuncSetAttribute(lstm_persist,
                             cudaFuncAttributeMaxDynamicSharedMemorySize,
                             196608);
        smem_set = 1;
    }

    // Phase 1: xw = x @ w_x^T + bias
    {
        dim3 grid(G4 / 128, (SEQ * BATCH) / 128);
        gemm_nt_bias<<<grid, 256>>>(x, w_x, bias, xw, SEQ * BATCH, G4, NIN);
    }

    // Phase 2: persistent recurrence (ONE launch)
    lstm_persist<<<NBLK, NTHR, 196608>>>(h0, c0, w_h);

    // Phase 3: pred = H @ w_o^T
    {
        dim3 grid(NHID / 128, (SEQ * BATCH) / 128);
        gemm_nt_bias<<<grid, 256>>>(hs, w_o, nullptr, out, SEQ * BATCH, NHID, NHID);
    }

    copy_tail<<<(BATCH * NHID + 255) / 256, 256>>>(
        out + (size_t)SEQ * BATCH * NHID,
        out + (size_t)SEQ * BATCH * NHID + BATCH * NHID);
}